// round 1
// baseline (speedup 1.0000x reference)
#include <cuda_runtime.h>
#include <cuda_bf16.h>

#define SEQ   8192
#define DIM   2048
#define H     16
#define HD    128           // head dim
#define PDIM  512           // proj dim
#define NCH   128           // row-chunks for weighted-sum partials (64 rows each)

// ---------------- scratch (device globals; no allocation allowed) ----------
__device__ float g_qprojT[DIM * H];          // [j][h]
__device__ float g_logits[H * SEQ];          // [h][s]
__device__ float g_attn[SEQ * H];            // [s][h]
__device__ float g_upart[(size_t)NCH * H * DIM]; // partial weighted sums
__device__ float g_u[H * DIM];               // [h][j]
__device__ float g_x1[DIM];
__device__ float g_h1[PDIM];
__device__ float g_g[PDIM];
__device__ float g_x1out[DIM];

// ---------------- reductions ----------------
__device__ __forceinline__ float blockReduceSum(float v) {
    __shared__ float sm[32];
    __syncthreads();
    int lane = threadIdx.x & 31, w = threadIdx.x >> 5;
    #pragma unroll
    for (int o = 16; o > 0; o >>= 1) v += __shfl_xor_sync(0xffffffffu, v, o);
    if (lane == 0) sm[w] = v;
    __syncthreads();
    int nw = blockDim.x >> 5;
    v = (threadIdx.x < nw) ? sm[threadIdx.x] : 0.f;
    if (w == 0) {
        #pragma unroll
        for (int o = 16; o > 0; o >>= 1) v += __shfl_xor_sync(0xffffffffu, v, o);
        if (lane == 0) sm[0] = v;
    }
    __syncthreads();
    return sm[0];
}

__device__ __forceinline__ float blockReduceMax(float v) {
    __shared__ float sm[32];
    __syncthreads();
    int lane = threadIdx.x & 31, w = threadIdx.x >> 5;
    #pragma unroll
    for (int o = 16; o > 0; o >>= 1) v = fmaxf(v, __shfl_xor_sync(0xffffffffu, v, o));
    if (lane == 0) sm[w] = v;
    __syncthreads();
    int nw = blockDim.x >> 5;
    v = (threadIdx.x < nw) ? sm[threadIdx.x] : -3.0e38f;
    if (w == 0) {
        #pragma unroll
        for (int o = 16; o > 0; o >>= 1) v = fmaxf(v, __shfl_xor_sync(0xffffffffu, v, o));
        if (lane == 0) sm[0] = v;
    }
    __syncthreads();
    return sm[0];
}

// ---------------- K1: qproj[h][j] = sum_d q[h*128+d] * W_kv[h*128+d][j] ----
// grid 128 (16 heads x 8 col-blocks), 256 threads
__global__ void k_qproj(const float* __restrict__ q, const float* __restrict__ Wkv) {
    int h  = blockIdx.x >> 3;
    int jb = blockIdx.x & 7;
    int j  = jb * 256 + threadIdx.x;
    __shared__ float sq[HD];
    if (threadIdx.x < HD) sq[threadIdx.x] = q[h * HD + threadIdx.x];
    __syncthreads();
    float acc = 0.f;
    #pragma unroll 8
    for (int d = 0; d < HD; d++)
        acc += sq[d] * Wkv[(size_t)(h * HD + d) * DIM + j];
    g_qprojT[j * H + h] = acc;
}

// ---------------- K2: logits[h][s] = x[s] . qproj[h] / sqrt(128) -----------
// warp per row; 1024 blocks x 256 threads
__global__ void k_logits(const float* __restrict__ x) {
    int warp = (blockIdx.x * blockDim.x + threadIdx.x) >> 5;
    int lane = threadIdx.x & 31;
    if (warp >= SEQ) return;
    int s = warp;
    const float4* x4 = (const float4*)x + (size_t)s * (DIM / 4);
    float acc[H];
    #pragma unroll
    for (int h = 0; h < H; h++) acc[h] = 0.f;
    #pragma unroll 2
    for (int i = 0; i < 16; i++) {
        int j4 = i * 32 + lane;
        float4 xv = __ldg(x4 + j4);
        #pragma unroll
        for (int e = 0; e < 4; e++) {
            float xe = (e == 0) ? xv.x : (e == 1) ? xv.y : (e == 2) ? xv.z : xv.w;
            const float4* qpe = (const float4*)(g_qprojT + (size_t)(j4 * 4 + e) * H);
            #pragma unroll
            for (int h4 = 0; h4 < 4; h4++) {
                float4 qv = qpe[h4];
                acc[h4 * 4 + 0] += xe * qv.x;
                acc[h4 * 4 + 1] += xe * qv.y;
                acc[h4 * 4 + 2] += xe * qv.z;
                acc[h4 * 4 + 3] += xe * qv.w;
            }
        }
    }
    #pragma unroll
    for (int h = 0; h < H; h++) {
        float v = acc[h];
        #pragma unroll
        for (int o = 16; o > 0; o >>= 1) v += __shfl_xor_sync(0xffffffffu, v, o);
        if (lane == 0) g_logits[h * SEQ + s] = v * 0.08838834764831845f; // 1/sqrt(128)
    }
}

// ---------------- K3: softmax per head; attn stored [s][h] -----------------
// 16 blocks x 256 threads
__global__ void k_softmax() {
    int h = blockIdx.x;
    const float* L = g_logits + (size_t)h * SEQ;
    float m = -3.0e38f;
    for (int i = threadIdx.x; i < SEQ; i += 256) m = fmaxf(m, L[i]);
    m = blockReduceMax(m);
    float z = 0.f;
    for (int i = threadIdx.x; i < SEQ; i += 256) z += __expf(L[i] - m);
    z = blockReduceSum(z);
    float inv = 1.f / z;
    for (int i = threadIdx.x; i < SEQ; i += 256)
        g_attn[(size_t)i * H + h] = __expf(L[i] - m) * inv;
}

// ---------------- K4: u_part[c][h][j] = sum_{s in chunk} attn[s][h]*x[s][j]
// grid (2 col-tiles, NCH chunks), 256 threads; each thread 4 cols (float4)
__global__ void k_wsum(const float* __restrict__ x) {
    int j4 = blockIdx.x * 256 + threadIdx.x;          // float4 column index
    int s0 = blockIdx.y * (SEQ / NCH);                // 64 rows per chunk
    const float4* x4 = (const float4*)x;
    const float4* a4 = (const float4*)g_attn;
    float4 acc[H];
    #pragma unroll
    for (int h = 0; h < H; h++) acc[h] = make_float4(0.f, 0.f, 0.f, 0.f);
    for (int ss = 0; ss < SEQ / NCH; ss++) {
        int s = s0 + ss;
        float4 xv = __ldg(x4 + (size_t)s * (DIM / 4) + j4);
        #pragma unroll
        for (int h4 = 0; h4 < 4; h4++) {
            float4 av = __ldg(a4 + (size_t)s * 4 + h4);
            float a0 = av.x, a1 = av.y, a2 = av.z, a3 = av.w;
            acc[h4*4+0].x += a0*xv.x; acc[h4*4+0].y += a0*xv.y; acc[h4*4+0].z += a0*xv.z; acc[h4*4+0].w += a0*xv.w;
            acc[h4*4+1].x += a1*xv.x; acc[h4*4+1].y += a1*xv.y; acc[h4*4+1].z += a1*xv.z; acc[h4*4+1].w += a1*xv.w;
            acc[h4*4+2].x += a2*xv.x; acc[h4*4+2].y += a2*xv.y; acc[h4*4+2].z += a2*xv.z; acc[h4*4+2].w += a2*xv.w;
            acc[h4*4+3].x += a3*xv.x; acc[h4*4+3].y += a3*xv.y; acc[h4*4+3].z += a3*xv.z; acc[h4*4+3].w += a3*xv.w;
        }
    }
    float* up = g_upart + (size_t)blockIdx.y * (H * DIM);
    #pragma unroll
    for (int h = 0; h < H; h++)
        ((float4*)(up + (size_t)h * DIM))[j4] = acc[h];
}

// ---------------- K4b: u[i] = sum_c u_part[c][i] ---------------------------
// 128 blocks x 256 threads, scalar coalesced
__global__ void k_ured() {
    int i = blockIdx.x * 256 + threadIdx.x;   // 0 .. H*DIM-1
    float s = 0.f;
    #pragma unroll 8
    for (int c = 0; c < NCH; c++)
        s += g_upart[(size_t)c * (H * DIM) + i];
    g_u[i] = s;
}

// ---------------- K5: x1[r] = b_v[r] + W_v[r] . u[r>>7] -------------------
// 2048 blocks x 256 threads
__global__ void k_xv(const float* __restrict__ Wkv, const float* __restrict__ bkv) {
    int r = blockIdx.x;
    const float4* w4 = (const float4*)(Wkv + (size_t)(DIM + r) * DIM);
    const float4* u4 = (const float4*)(g_u + (size_t)(r >> 7) * DIM);
    float acc = 0.f;
    for (int i = threadIdx.x; i < DIM / 4; i += 256) {
        float4 a = __ldg(w4 + i), b = u4[i];
        acc += a.x * b.x + a.y * b.y + a.z * b.z + a.w * b.w;
    }
    acc = blockReduceSum(acc);
    if (threadIdx.x == 0) g_x1[r] = acc + bkv[DIM + r];
}

// ---------------- generic GEMV: out[r] = b[r] + W[r] . v -------------------
__global__ void k_gemv(const float* __restrict__ W, const float* __restrict__ v,
                       const float* __restrict__ b, float* __restrict__ out,
                       int ncols4) {
    int r = blockIdx.x;
    const float4* w4 = (const float4*)(W + (size_t)r * (ncols4 * 4));
    const float4* v4 = (const float4*)v;
    float acc = 0.f;
    for (int i = threadIdx.x; i < ncols4; i += 256) {
        float4 a = __ldg(w4 + i), c = v4[i];
        acc += a.x * c.x + a.y * c.y + a.z * c.z + a.w * c.w;
    }
    acc = blockReduceSum(acc);
    if (threadIdx.x == 0) out[r] = acc + b[r];
}

// ---------------- K6b: LayerNorm + ReLU over h1[512] -----------------------
// 1 block x 512 threads
__global__ void k_ln(const float* __restrict__ ln_w, const float* __restrict__ ln_b) {
    int t = threadIdx.x;
    float v = g_h1[t];
    float mu = blockReduceSum(v) * (1.f / PDIM);
    float d = v - mu;
    float var = blockReduceSum(d * d) * (1.f / PDIM);
    float g = d * rsqrtf(var + 1e-5f) * ln_w[t] + ln_b[t];
    g_g[t] = fmaxf(g, 0.f);
}

// ---------------- K8: out[s][j] = x[s][j] + x1out[j] -----------------------
__global__ void k_resid(const float* __restrict__ x, float* __restrict__ out) {
    size_t i = (size_t)blockIdx.x * blockDim.x + threadIdx.x; // float4 index
    float4 xv = ((const float4*)x)[i];
    float4 a  = __ldg((const float4*)g_x1out + (i & (DIM / 4 - 1)));
    xv.x += a.x; xv.y += a.y; xv.z += a.z; xv.w += a.w;
    ((float4*)out)[i] = xv;
}

extern "C" void kernel_launch(void* const* d_in, const int* in_sizes, int n_in,
                              void* d_out, int out_size) {
    const float* x    = (const float*)d_in[0];
    const float* q    = (const float*)d_in[1];
    const float* Wkv  = (const float*)d_in[2];
    const float* bkv  = (const float*)d_in[3];
    const float* Wp1  = (const float*)d_in[4];
    const float* bp1  = (const float*)d_in[5];
    const float* Wp2  = (const float*)d_in[6];
    const float* bp2  = (const float*)d_in[7];
    const float* lnw  = (const float*)d_in[8];
    const float* lnb  = (const float*)d_in[9];
    float* out = (float*)d_out;

    float* d_x1;    cudaGetSymbolAddress((void**)&d_x1,    g_x1);
    float* d_h1;    cudaGetSymbolAddress((void**)&d_h1,    g_h1);
    float* d_g;     cudaGetSymbolAddress((void**)&d_g,     g_g);
    float* d_x1out; cudaGetSymbolAddress((void**)&d_x1out, g_x1out);

    k_qproj  <<<128, 256>>>(q, Wkv);
    k_logits <<<SEQ * 32 / 256, 256>>>(x);
    k_softmax<<<H, 256>>>();
    {
        dim3 grid(2, NCH);
        k_wsum<<<grid, 256>>>(x);
    }
    k_ured   <<<H * DIM / 256, 256>>>();
    k_xv     <<<DIM, 256>>>(Wkv, bkv);
    k_gemv   <<<PDIM, 256>>>(Wp1, d_x1, bp1, d_h1, DIM / 4);
    k_ln     <<<1, PDIM>>>(lnw, lnb);
    k_gemv   <<<DIM, 256>>>(Wp2, d_g, bp2, d_x1out, PDIM / 4);
    k_resid  <<<(SEQ * DIM / 4) / 256, 256>>>(x, out);
}

// round 2
// speedup vs baseline: 2.7551x; 2.7551x over previous
#include <cuda_runtime.h>
#include <cuda_bf16.h>

#define SEQ   8192
#define DIM   2048
#define H     16
#define HD    128           // head dim
#define PDIM  512           // proj dim
#define NCH   128           // row-chunks for weighted-sum partials (64 rows each)
#define WROWS (SEQ / NCH)   // 64 rows per chunk

// ---------------- scratch (device globals; no allocation allowed) ----------
__device__ float g_qprojH[H * DIM];          // [h][j]
__device__ float g_logits[SEQ * H];          // [s][h]
__device__ float g_attn[SEQ * H];            // [s][h]
__device__ float g_upart[(size_t)NCH * H * DIM]; // partial weighted sums
__device__ float g_u[H * DIM];               // [h][j]
__device__ float g_x1[DIM];
__device__ float g_h1[PDIM];
__device__ float g_g[PDIM];
__device__ float g_x1out[DIM];

// ---------------- f32x2 packed FMA helpers ---------------------------------
union F2U { unsigned long long u; float2 f; };

__device__ __forceinline__ void ffma2(unsigned long long& d,
                                      unsigned long long a,
                                      unsigned long long b) {
    asm("fma.rn.f32x2 %0, %1, %2, %0;" : "+l"(d) : "l"(a), "l"(b));
}
__device__ __forceinline__ unsigned long long pack2(float lo, float hi) {
    unsigned long long r;
    asm("mov.b64 %0, {%1, %2};" : "=l"(r) : "f"(lo), "f"(hi));
    return r;
}

// ---------------- reductions ----------------
__device__ __forceinline__ float blockReduceSum(float v) {
    __shared__ float sm[32];
    __syncthreads();
    int lane = threadIdx.x & 31, w = threadIdx.x >> 5;
    #pragma unroll
    for (int o = 16; o > 0; o >>= 1) v += __shfl_xor_sync(0xffffffffu, v, o);
    if (lane == 0) sm[w] = v;
    __syncthreads();
    int nw = blockDim.x >> 5;
    v = (threadIdx.x < nw) ? sm[threadIdx.x] : 0.f;
    if (w == 0) {
        #pragma unroll
        for (int o = 16; o > 0; o >>= 1) v += __shfl_xor_sync(0xffffffffu, v, o);
        if (lane == 0) sm[0] = v;
    }
    __syncthreads();
    return sm[0];
}

__device__ __forceinline__ float blockReduceMax(float v) {
    __shared__ float sm[32];
    __syncthreads();
    int lane = threadIdx.x & 31, w = threadIdx.x >> 5;
    #pragma unroll
    for (int o = 16; o > 0; o >>= 1) v = fmaxf(v, __shfl_xor_sync(0xffffffffu, v, o));
    if (lane == 0) sm[w] = v;
    __syncthreads();
    int nw = blockDim.x >> 5;
    v = (threadIdx.x < nw) ? sm[threadIdx.x] : -3.0e38f;
    if (w == 0) {
        #pragma unroll
        for (int o = 16; o > 0; o >>= 1) v = fmaxf(v, __shfl_xor_sync(0xffffffffu, v, o));
        if (lane == 0) sm[0] = v;
    }
    __syncthreads();
    return sm[0];
}

// ---------------- K1: qprojH[h][j] = sum_d q[h*128+d] * W_kv[h*128+d][j] ---
// grid 128 (16 heads x 8 col-blocks), 256 threads
__global__ void k_qproj(const float* __restrict__ q, const float* __restrict__ Wkv) {
    int h  = blockIdx.x >> 3;
    int jb = blockIdx.x & 7;
    int j  = jb * 256 + threadIdx.x;
    __shared__ float sq[HD];
    if (threadIdx.x < HD) sq[threadIdx.x] = q[h * HD + threadIdx.x];
    __syncthreads();
    float acc = 0.f;
    #pragma unroll 8
    for (int d = 0; d < HD; d++)
        acc += sq[d] * Wkv[(size_t)(h * HD + d) * DIM + j];
    g_qprojH[h * DIM + j] = acc;
}

// ---------------- K2: logits[s][h] = x[s] . qproj[h] / sqrt(128) -----------
// block = 256 threads = 8 warps, each warp owns 4 rows; 256 blocks
// qproj staged in smem as [h][j-tile], conflict-free scalar LDS.
__global__ void __launch_bounds__(256) k_logits(const float* __restrict__ x) {
    __shared__ float qs[H][256];
    int t = threadIdx.x, lane = t & 31, warp = t >> 5;
    int row0 = blockIdx.x * 32 + warp * 4;
    float acc[4][H];
    #pragma unroll
    for (int r = 0; r < 4; r++)
        #pragma unroll
        for (int h = 0; h < H; h++) acc[r][h] = 0.f;

    for (int jt = 0; jt < DIM; jt += 256) {
        __syncthreads();
        #pragma unroll
        for (int r = 0; r < 4; r++) {
            int idx = t + r * 256;      // 0..1023 -> (h, 64 float4 per row)
            int h = idx >> 6;
            int jj = idx & 63;
            ((float4*)qs[h])[jj] =
                __ldg((const float4*)(g_qprojH + (size_t)h * DIM + jt) + jj);
        }
        __syncthreads();
        #pragma unroll
        for (int i = 0; i < 8; i++) {
            int j = i * 32 + lane;
            const float* xp = x + jt + j;
            float x0 = __ldg(xp + (size_t)(row0 + 0) * DIM);
            float x1 = __ldg(xp + (size_t)(row0 + 1) * DIM);
            float x2 = __ldg(xp + (size_t)(row0 + 2) * DIM);
            float x3 = __ldg(xp + (size_t)(row0 + 3) * DIM);
            #pragma unroll
            for (int h = 0; h < H; h++) {
                float w = qs[h][j];
                acc[0][h] += x0 * w;
                acc[1][h] += x1 * w;
                acc[2][h] += x2 * w;
                acc[3][h] += x3 * w;
            }
        }
    }
    const float scale = 0.08838834764831845f; // 1/sqrt(128)
    #pragma unroll
    for (int r = 0; r < 4; r++) {
        float out = 0.f;
        #pragma unroll
        for (int h = 0; h < H; h++) {
            float v = acc[r][h];
            #pragma unroll
            for (int o = 16; o > 0; o >>= 1) v += __shfl_xor_sync(0xffffffffu, v, o);
            if (lane == h) out = v;
        }
        if (lane < H)
            g_logits[(size_t)(row0 + r) * H + lane] = out * scale;
    }
}

// ---------------- K3: softmax per head; logits/attn in [s][h] --------------
// 16 blocks x 256 threads
__global__ void k_softmax() {
    int h = blockIdx.x;
    float m = -3.0e38f;
    for (int i = threadIdx.x; i < SEQ; i += 256)
        m = fmaxf(m, g_logits[(size_t)i * H + h]);
    m = blockReduceMax(m);
    float z = 0.f;
    for (int i = threadIdx.x; i < SEQ; i += 256)
        z += __expf(g_logits[(size_t)i * H + h] - m);
    z = blockReduceSum(z);
    float inv = 1.f / z;
    for (int i = threadIdx.x; i < SEQ; i += 256)
        g_attn[(size_t)i * H + h] = __expf(g_logits[(size_t)i * H + h] - m) * inv;
}

// ---------------- K4: u_part[c][h][j] = sum_{s in chunk} attn[s][h]*x[s][j]
// grid (2 col-tiles, NCH chunks), 256 threads; thread owns 4 cols (float4);
// attn chunk staged in smem; head-pairs packed into f32x2 FFMA.
__global__ void __launch_bounds__(256) k_wsum(const float* __restrict__ x) {
    __shared__ float sa[WROWS * H];     // 64 rows x 16 heads = 4 KB
    int t = threadIdx.x;
    int j4 = blockIdx.x * 256 + t;
    int s0 = blockIdx.y * WROWS;
    // cooperative load of attn chunk (1024 floats = 256 float4)
    ((float4*)sa)[t] = __ldg((const float4*)(g_attn + (size_t)s0 * H) + t);
    __syncthreads();

    unsigned long long acc[8][4];       // [head-pair][col] : (head 2hp, 2hp+1)
    #pragma unroll
    for (int hp = 0; hp < 8; hp++)
        #pragma unroll
        for (int c = 0; c < 4; c++) acc[hp][c] = 0ull;

    const float4* x4 = (const float4*)x;
    #pragma unroll 2
    for (int r = 0; r < WROWS; r++) {
        float4 xv = __ldg(x4 + (size_t)(s0 + r) * (DIM / 4) + j4);
        unsigned long long xp[4];
        xp[0] = pack2(xv.x, xv.x);
        xp[1] = pack2(xv.y, xv.y);
        xp[2] = pack2(xv.z, xv.z);
        xp[3] = pack2(xv.w, xv.w);
        const float2* arow = (const float2*)(sa + r * H);
        #pragma unroll
        for (int hp = 0; hp < 8; hp++) {
            float2 a = arow[hp];        // broadcast LDS.64
            unsigned long long ap = pack2(a.x, a.y);
            ffma2(acc[hp][0], ap, xp[0]);
            ffma2(acc[hp][1], ap, xp[1]);
            ffma2(acc[hp][2], ap, xp[2]);
            ffma2(acc[hp][3], ap, xp[3]);
        }
    }
    float* up = g_upart + (size_t)blockIdx.y * (H * DIM);
    #pragma unroll
    for (int hp = 0; hp < 8; hp++) {
        F2U u0, u1, u2, u3;
        u0.u = acc[hp][0]; u1.u = acc[hp][1]; u2.u = acc[hp][2]; u3.u = acc[hp][3];
        float4 lo = make_float4(u0.f.x, u1.f.x, u2.f.x, u3.f.x);
        float4 hi = make_float4(u0.f.y, u1.f.y, u2.f.y, u3.f.y);
        ((float4*)(up + (size_t)(2 * hp + 0) * DIM))[j4] = lo;
        ((float4*)(up + (size_t)(2 * hp + 1) * DIM))[j4] = hi;
    }
}

// ---------------- K4b: u[i] = sum_c u_part[c][i] ---------------------------
__global__ void k_ured() {
    int i = blockIdx.x * 256 + threadIdx.x;   // 0 .. H*DIM-1
    float s = 0.f;
    #pragma unroll 8
    for (int c = 0; c < NCH; c++)
        s += g_upart[(size_t)c * (H * DIM) + i];
    g_u[i] = s;
}

// ---------------- K5: x1[r] = b_v[r] + W_v[r] . u[r>>7] -------------------
__global__ void k_xv(const float* __restrict__ Wkv, const float* __restrict__ bkv) {
    int r = blockIdx.x;
    const float4* w4 = (const float4*)(Wkv + (size_t)(DIM + r) * DIM);
    const float4* u4 = (const float4*)(g_u + (size_t)(r >> 7) * DIM);
    float acc = 0.f;
    for (int i = threadIdx.x; i < DIM / 4; i += 256) {
        float4 a = __ldg(w4 + i), b = u4[i];
        acc += a.x * b.x + a.y * b.y + a.z * b.z + a.w * b.w;
    }
    acc = blockReduceSum(acc);
    if (threadIdx.x == 0) g_x1[r] = acc + bkv[DIM + r];
}

// ---------------- generic GEMV: out[r] = b[r] + W[r] . v -------------------
__global__ void k_gemv(const float* __restrict__ W, const float* __restrict__ v,
                       const float* __restrict__ b, float* __restrict__ out,
                       int ncols4) {
    int r = blockIdx.x;
    const float4* w4 = (const float4*)(W + (size_t)r * (ncols4 * 4));
    const float4* v4 = (const float4*)v;
    float acc = 0.f;
    for (int i = threadIdx.x; i < ncols4; i += 256) {
        float4 a = __ldg(w4 + i), c = v4[i];
        acc += a.x * c.x + a.y * c.y + a.z * c.z + a.w * c.w;
    }
    acc = blockReduceSum(acc);
    if (threadIdx.x == 0) out[r] = acc + b[r];
}

// ---------------- K6b: LayerNorm + ReLU over h1[512] -----------------------
__global__ void k_ln(const float* __restrict__ ln_w, const float* __restrict__ ln_b) {
    int t = threadIdx.x;
    float v = g_h1[t];
    float mu = blockReduceSum(v) * (1.f / PDIM);
    float d = v - mu;
    float var = blockReduceSum(d * d) * (1.f / PDIM);
    float g = d * rsqrtf(var + 1e-5f) * ln_w[t] + ln_b[t];
    g_g[t] = fmaxf(g, 0.f);
}

// ---------------- K8: out[s][j] = x[s][j] + x1out[j] -----------------------
__global__ void k_resid(const float* __restrict__ x, float* __restrict__ out) {
    size_t i = (size_t)blockIdx.x * blockDim.x + threadIdx.x; // float4 index
    float4 xv = ((const float4*)x)[i];
    float4 a  = __ldg((const float4*)g_x1out + (i & (DIM / 4 - 1)));
    xv.x += a.x; xv.y += a.y; xv.z += a.z; xv.w += a.w;
    ((float4*)out)[i] = xv;
}

extern "C" void kernel_launch(void* const* d_in, const int* in_sizes, int n_in,
                              void* d_out, int out_size) {
    const float* x    = (const float*)d_in[0];
    const float* q    = (const float*)d_in[1];
    const float* Wkv  = (const float*)d_in[2];
    const float* bkv  = (const float*)d_in[3];
    const float* Wp1  = (const float*)d_in[4];
    const float* bp1  = (const float*)d_in[5];
    const float* Wp2  = (const float*)d_in[6];
    const float* bp2  = (const float*)d_in[7];
    const float* lnw  = (const float*)d_in[8];
    const float* lnb  = (const float*)d_in[9];
    float* out = (float*)d_out;

    float* d_x1;    cudaGetSymbolAddress((void**)&d_x1,    g_x1);
    float* d_h1;    cudaGetSymbolAddress((void**)&d_h1,    g_h1);
    float* d_g;     cudaGetSymbolAddress((void**)&d_g,     g_g);
    float* d_x1out; cudaGetSymbolAddress((void**)&d_x1out, g_x1out);

    k_qproj  <<<128, 256>>>(q, Wkv);
    k_logits <<<SEQ / 32, 256>>>(x);
    k_softmax<<<H, 256>>>();
    {
        dim3 grid(DIM / 4 / 256, NCH);
        k_wsum<<<grid, 256>>>(x);
    }
    k_ured   <<<H * DIM / 256, 256>>>();
    k_xv     <<<DIM, 256>>>(Wkv, bkv);
    k_gemv   <<<PDIM, 256>>>(Wp1, d_x1, bp1, d_h1, DIM / 4);
    k_ln     <<<1, PDIM>>>(lnw, lnb);
    k_gemv   <<<DIM, 256>>>(Wp2, d_g, bp2, d_x1out, PDIM / 4);
    k_resid  <<<(SEQ * DIM / 4) / 256, 256>>>(x, out);
}